// round 12
// baseline (speedup 1.0000x reference)
#include <cuda_runtime.h>
#include <cuda_bf16.h>
#include <cstdint>

#define B_ 8
#define T_ 2048
#define C_ 1024
#define H_ 64
#define M_TOTAL (B_ * T_)   // 16384 rows

// bf16 hi/lo split scratch (allocation-free rule: __device__ globals)
__device__ __align__(16) __nv_bfloat16 g_qh[M_TOTAL * H_];
__device__ __align__(16) __nv_bfloat16 g_ql[M_TOTAL * H_];
__device__ __align__(16) __nv_bfloat16 g_kh[M_TOTAL * H_];
__device__ __align__(16) __nv_bfloat16 g_kl[M_TOTAL * H_];
// V stored transposed per batch: [b][h][t]
__device__ __align__(16) __nv_bfloat16 g_vth[B_ * H_ * T_];
__device__ __align__(16) __nv_bfloat16 g_vtl[B_ * H_ * T_];
// Fused weight, transposed + split: row n = {q0..63, k0..63, v0..63}, k-major
__device__ __align__(16) __nv_bfloat16 g_wth[192 * 1024];
__device__ __align__(16) __nv_bfloat16 g_wtl[192 * 1024];
// Split-K partials: 8 batches x 16 heavy q-tiles x 2 splits
__device__ __align__(16) float g_pU[256 * 4096];
__device__ float g_pm[256 * 64];
__device__ float g_pl[256 * 64];

// ---------------------------------------------------------------------------
// Base-PTX helpers (sm_80+ only; compute_103 virtual arch blocks tcgen05)
// ---------------------------------------------------------------------------
__device__ __forceinline__ uint32_t smem_u32(const void* p) {
  uint32_t a;
  asm("{ .reg .u64 t; cvta.to.shared.u64 t, %1; cvt.u32.u64 %0, t; }"
      : "=r"(a) : "l"(p));
  return a;
}

__device__ __forceinline__ void mma_bf16(float d[4], const unsigned a[4],
                                         unsigned b0, unsigned b1) {
  asm volatile(
      "mma.sync.aligned.m16n8k16.row.col.f32.bf16.bf16.f32 "
      "{%0,%1,%2,%3}, {%4,%5,%6,%7}, {%8,%9}, {%0,%1,%2,%3};\n"
      : "+f"(d[0]), "+f"(d[1]), "+f"(d[2]), "+f"(d[3])
      : "r"(a[0]), "r"(a[1]), "r"(a[2]), "r"(a[3]), "r"(b0), "r"(b1));
}

__device__ __forceinline__ void ldsm4(unsigned r[4], uint32_t addr) {
  asm volatile(
      "ldmatrix.sync.aligned.m8n8.x4.shared.b16 {%0,%1,%2,%3}, [%4];\n"
      : "=r"(r[0]), "=r"(r[1]), "=r"(r[2]), "=r"(r[3]) : "r"(addr));
}

#define CP_ASYNC16(dst, src) \
  asm volatile("cp.async.cg.shared.global [%0], [%1], 16;\n" \
               :: "r"(dst), "l"(src))
#define CP_COMMIT() asm volatile("cp.async.commit_group;\n" ::: "memory")
#define CP_WAIT0()  asm volatile("cp.async.wait_group 0;\n" ::: "memory")

#define LDU(p) (*(const unsigned*)&(p))

// ---------------------------------------------------------------------------
// Kernel 0: coalesced weight transpose + hi/lo split (48 blocks). Unchanged.
// ---------------------------------------------------------------------------
__global__ __launch_bounds__(256) void wsplit_kernel(
    const float* __restrict__ Wq, const float* __restrict__ Wk,
    const float* __restrict__ Wv) {
  __shared__ float tile[64][65];
  const int t = threadIdx.x;
  const int w = blockIdx.x >> 4;          // 0..2
  const int k0 = (blockIdx.x & 15) * 64;  // k tile
  const float* W = (w == 0) ? Wq : (w == 1 ? Wk : Wv);

#pragma unroll
  for (int i = 0; i < 16; i++) {
    int idx = i * 256 + t;
    int r = idx >> 6, c = idx & 63;
    tile[r][c] = W[(size_t)(k0 + r) * H_ + c];
  }
  __syncthreads();

  const int h = t >> 2, seg = t & 3;
  union { __nv_bfloat16 b[16]; uint4 u[2]; } th, tl;
#pragma unroll
  for (int kk = 0; kk < 16; kk++) {
    float v = tile[seg * 16 + kk][h];
    __nv_bfloat16 hi = __float2bfloat16(v);
    th.b[kk] = hi;
    tl.b[kk] = __float2bfloat16(v - __bfloat162float(hi));
  }
  size_t base = (size_t)(w * 64 + h) * C_ + k0 + seg * 16;
  ((uint4*)(g_wth + base))[0] = th.u[0];
  ((uint4*)(g_wth + base))[1] = th.u[1];
  ((uint4*)(g_wtl + base))[0] = tl.u[0];
  ((uint4*)(g_wtl + base))[1] = tl.u[1];
}

// ---------------------------------------------------------------------------
// Kernel 1: QKV GEMM on legacy tensor cores (unchanged, measured ~56us).
// ---------------------------------------------------------------------------
#define A_STRIDE_B 80            // bytes per A/B smem row (40 bf16)
#define OFF_AH 0
#define OFF_AL 10240             // 128*80
#define OFF_BH 20480
#define OFF_BL 35840             // +192*80
#define ST_BYTES 51200
#define QKV_SMEM (2 * ST_BYTES)  // 102400
#define VTS 66                   // V transpose tile stride (bf16 elems)

__global__ __launch_bounds__(256, 1) void qkv_mma(const float* __restrict__ x) {
  extern __shared__ char sm[];
  const uint32_t sb = smem_u32(sm);
  const int t = threadIdx.x;
  const int lane = t & 31, warp = t >> 5;
  const int g = lane >> 2, c = lane & 3;
  const int lm = lane >> 3, lr = lane & 7;
  const int wm = warp >> 1, wn = warp & 1;   // 4(M) x 2(N)
  const int row0 = blockIdx.x * 128;

  float acc[2][12][4];
#pragma unroll
  for (int mt = 0; mt < 2; mt++)
#pragma unroll
    for (int nt = 0; nt < 12; nt++)
#pragma unroll
      for (int r = 0; r < 4; r++) acc[mt][nt][r] = 0.f;

  const int arow = t >> 1, ahalf = t & 1;
  const float* xptr = x + (size_t)(row0 + arow) * C_ + ahalf * 16;

  uint32_t aoff[2][2], boff[6][2];
#pragma unroll
  for (int mt = 0; mt < 2; mt++)
#pragma unroll
    for (int ks = 0; ks < 2; ks++)
      aoff[mt][ks] = (uint32_t)((wm * 32 + mt * 16 + (lm & 1) * 8 + lr) * A_STRIDE_B +
                                (ks * 16 + (lm >> 1) * 8) * 2);
#pragma unroll
  for (int pair = 0; pair < 6; pair++)
#pragma unroll
    for (int ks = 0; ks < 2; ks++)
      boff[pair][ks] = (uint32_t)((wn * 96 + pair * 16 + (lm >> 1) * 8 + lr) * A_STRIDE_B +
                                  (ks * 16 + (lm & 1) * 8) * 2);

  auto storeA = [&](uint32_t base, const float4 xr[4]) {
    union { __nv_bfloat16 b[16]; uint4 u[2]; } hu, lu;
#pragma unroll
    for (int v4 = 0; v4 < 4; v4++) {
      const float* f = (const float*)&xr[v4];
#pragma unroll
      for (int e = 0; e < 4; e++) {
        __nv_bfloat16 hi = __float2bfloat16(f[e]);
        hu.b[v4 * 4 + e] = hi;
        lu.b[v4 * 4 + e] = __float2bfloat16(f[e] - __bfloat162float(hi));
      }
    }
    char* dst_h = sm + (base - sb) + OFF_AH + arow * A_STRIDE_B + ahalf * 32;
    char* dst_l = sm + (base - sb) + OFF_AL + arow * A_STRIDE_B + ahalf * 32;
    ((uint4*)dst_h)[0] = hu.u[0];
    ((uint4*)dst_h)[1] = hu.u[1];
    ((uint4*)dst_l)[0] = lu.u[0];
    ((uint4*)dst_l)[1] = lu.u[1];
  };

  auto issueB = [&](int kc, uint32_t base) {
#pragma unroll
    for (int i = 0; i < 3; i++) {
      int f = i * 256 + t;
      int row = f >> 2, seg = f & 3;
      uint32_t dh = base + OFF_BH + row * A_STRIDE_B + seg * 16;
      uint32_t dl = base + OFF_BL + row * A_STRIDE_B + seg * 16;
      const __nv_bfloat16* sh = g_wth + (size_t)row * C_ + kc * 32 + seg * 8;
      const __nv_bfloat16* sl = g_wtl + (size_t)row * C_ + kc * 32 + seg * 8;
      CP_ASYNC16(dh, sh);
      CP_ASYNC16(dl, sl);
    }
  };

  float4 xr[4];
#pragma unroll
  for (int i = 0; i < 4; i++) xr[i] = *(const float4*)(xptr + i * 4);
  storeA(sb, xr);
  issueB(0, sb);
  CP_COMMIT();
#pragma unroll
  for (int i = 0; i < 4; i++) xr[i] = *(const float4*)(xptr + 32 + i * 4);

  for (int kc = 0; kc < 32; kc++) {
    const uint32_t sbase = sb + (kc & 1) * ST_BYTES;
    const uint32_t nbase = sb + ((kc & 1) ^ 1) * ST_BYTES;

    CP_WAIT0();
    __syncthreads();

    if (kc + 1 < 32) {
      issueB(kc + 1, nbase);
      CP_COMMIT();
    }

#pragma unroll
    for (int ks = 0; ks < 2; ks++) {
      unsigned ah[2][4], al[2][4];
#pragma unroll
      for (int mt = 0; mt < 2; mt++) {
        ldsm4(ah[mt], sbase + OFF_AH + aoff[mt][ks]);
        ldsm4(al[mt], sbase + OFF_AL + aoff[mt][ks]);
      }
#pragma unroll
      for (int pair = 0; pair < 6; pair++) {
        unsigned bh[4], bl[4];
        ldsm4(bh, sbase + OFF_BH + boff[pair][ks]);
        ldsm4(bl, sbase + OFF_BL + boff[pair][ks]);
#pragma unroll
        for (int sub = 0; sub < 2; sub++) {
          const int nt = pair * 2 + sub;
          unsigned b0h = bh[sub * 2], b1h = bh[sub * 2 + 1];
          unsigned b0l = bl[sub * 2], b1l = bl[sub * 2 + 1];
#pragma unroll
          for (int mt = 0; mt < 2; mt++) {
            mma_bf16(acc[mt][nt], ah[mt], b0h, b1h);
            mma_bf16(acc[mt][nt], ah[mt], b0l, b1l);
            mma_bf16(acc[mt][nt], al[mt], b0h, b1h);
          }
        }
      }
    }

    if (kc + 1 < 32) {
      storeA(nbase, xr);
      if (kc + 2 < 32) {
#pragma unroll
        for (int i = 0; i < 4; i++)
          xr[i] = *(const float4*)(xptr + (kc + 2) * 32 + i * 4);
      }
    }
  }

#pragma unroll
  for (int mt = 0; mt < 2; mt++) {
#pragma unroll
    for (int nt = 0; nt < 12; nt++) {
      const int n0 = wn * 96 + nt * 8;
      const int arr = n0 >> 6;
      if (arr < 2) {
        __nv_bfloat16* dh = arr ? g_kh : g_qh;
        __nv_bfloat16* dl = arr ? g_kl : g_ql;
        const int hcol = (n0 & 63) + 2 * c;
#pragma unroll
        for (int half = 0; half < 2; half++) {
          float d0 = acc[mt][nt][half * 2], d1 = acc[mt][nt][half * 2 + 1];
          int row = row0 + wm * 32 + mt * 16 + g + half * 8;
          __nv_bfloat162 h2 = __floats2bfloat162_rn(d0, d1);
          float2 hf = __bfloat1622float2(h2);
          __nv_bfloat162 l2 = __floats2bfloat162_rn(d0 - hf.x, d1 - hf.y);
          *(unsigned*)&dh[(size_t)row * H_ + hcol] = *(unsigned*)&h2;
          *(unsigned*)&dl[(size_t)row * H_ + hcol] = *(unsigned*)&l2;
        }
      }
    }
  }

  __syncthreads();
  __nv_bfloat16* Vsh = (__nv_bfloat16*)sm;
  __nv_bfloat16* Vsl = (__nv_bfloat16*)(sm + 128 * VTS * 2);
  if (wn == 1) {
#pragma unroll
    for (int mt = 0; mt < 2; mt++) {
#pragma unroll
      for (int nt = 4; nt < 12; nt++) {
        const int n0 = 96 + nt * 8;
        const int vcol = (n0 - 128) + 2 * c;
#pragma unroll
        for (int half = 0; half < 2; half++) {
          float d0 = acc[mt][nt][half * 2], d1 = acc[mt][nt][half * 2 + 1];
          int rl = wm * 32 + mt * 16 + g + half * 8;
          __nv_bfloat162 h2 = __floats2bfloat162_rn(d0, d1);
          float2 hf = __bfloat1622float2(h2);
          __nv_bfloat162 l2 = __floats2bfloat162_rn(d0 - hf.x, d1 - hf.y);
          *(unsigned*)&Vsh[rl * VTS + vcol] = *(unsigned*)&h2;
          *(unsigned*)&Vsl[rl * VTS + vcol] = *(unsigned*)&l2;
        }
      }
    }
  }
  __syncthreads();
  {
    const int h = t & 63, q = t >> 6;
    const int bb = row0 >> 11;
    const int tt0 = row0 & 2047;
    union { __nv_bfloat16 b[32]; uint4 u[4]; } th, tl;
#pragma unroll
    for (int i = 0; i < 32; i++) {
      th.b[i] = Vsh[(q * 32 + i) * VTS + h];
      tl.b[i] = Vsl[(q * 32 + i) * VTS + h];
    }
    __nv_bfloat16* dh = g_vth + (size_t)(bb * H_ + h) * T_ + tt0 + q * 32;
    __nv_bfloat16* dl = g_vtl + (size_t)(bb * H_ + h) * T_ + tt0 + q * 32;
#pragma unroll
    for (int u = 0; u < 4; u++) {
      ((uint4*)dh)[u] = th.u[u];
      ((uint4*)dl)[u] = tl.u[u];
    }
  }
}

// ---------------------------------------------------------------------------
// Kernel 2: causal flash attention, FA2-style M-only warp split.
// 128 threads = 4 warps x 16 q-rows; each warp owns full 64-key rows.
// Softmax is thread-local + 2 shfls; S accumulators convert in-register to
// PV A-fragments (no P smem round-trip, no named barriers, no red arrays).
// Schedule = R10 split-K: grid 8 x 48; units 3i/3i+1 = halves of qt=31-i,
// unit 3i+2 = qt=15-i single. smem = double-buffered KV only (73728 B).
// ---------------------------------------------------------------------------
#define SKS 72
#define TILE_ELEMS (64 * SKS)                // 4608 bf16
#define TILE_B (TILE_ELEMS * 2)              // 9216 bytes
#define KVBUF_B (4 * TILE_B)                 // 36864 bytes per buffer
#define JP_OFF (16 * SKS * 2)                // 2304: +16 n-rows
#define ATT_SMEM_BYTES (2 * KVBUF_B)         // 73728

__global__ __launch_bounds__(128, 3) void attn_kernel(float* __restrict__ out) {
  extern __shared__ __nv_bfloat16 smb[];
  const uint32_t smb_u = smem_u32(smb);

  const int t = threadIdx.x;
  const int warp = t >> 5, lane = t & 31;
  const int g = lane >> 2, c = lane & 3;
  const int lm = lane >> 3, lr = lane & 7;
  const int bx = blockIdx.x;
  const int b  = bx & 7;
  const int u  = bx >> 3;                   // 0..47
  const int stepi = u / 3;
  const int r3 = u - stepi * 3;

  int qt, kt0, kt1, split;
  bool is_split;
  if (r3 < 2) {
    qt = 31 - stepi;
    split = r3;
    int nk = qt + 1, half = nk >> 1;
    kt0 = split ? half : 0;
    kt1 = split ? nk : half;
    is_split = true;
  } else {
    qt = 15 - stepi;
    split = 0;
    kt0 = 0;
    kt1 = qt + 1;
    is_split = false;
  }

  const int bT = b * T_;
  const int qbase = qt * 64;

  // ldmatrix lane base (bytes), buffer-relative: n-block=lm>>1, k-block=lm&1
  const uint32_t bL = (uint32_t)(((lm >> 1) * 8 + lr) * SKS + (lm & 1) * 8) * 2;

  // ---- cp.async staging of one K/V tile into a buffer (128 threads) ----
  auto issue_tile = [&](int kbase, uint32_t bufb) {
#pragma unroll
    for (int ii = 0; ii < 4; ii++) {
      int id = ii * 128 + t;
      int r = id >> 3, s = id & 7;
      uint32_t rowoff = (uint32_t)(r * (SKS * 2) + s * 16);
      CP_ASYNC16(bufb + rowoff,
                 g_kh + (size_t)(bT + kbase + r) * H_ + s * 8);
      CP_ASYNC16(bufb + TILE_B + rowoff,
                 g_kl + (size_t)(bT + kbase + r) * H_ + s * 8);
      CP_ASYNC16(bufb + 2 * TILE_B + rowoff,
                 g_vth + (size_t)(b * 64 + r) * T_ + kbase + s * 8);
      CP_ASYNC16(bufb + 3 * TILE_B + rowoff,
                 g_vtl + (size_t)(b * 64 + r) * T_ + kbase + s * 8);
    }
    CP_COMMIT();
  };

  // ---- Q A-fragments, register-resident (warp rows = warp*16 + g/g+8) ----
  unsigned qfh[4][4], qfl[4][4];
  {
    const unsigned* qhp = (const unsigned*)g_qh;
    const unsigned* qlp = (const unsigned*)g_ql;
    int r0 = (bT + qbase + warp * 16 + g) * 32;
    int r8 = r0 + 8 * 32;
#pragma unroll
    for (int ks = 0; ks < 4; ks++) {
      int off = ks * 8 + c;
      qfh[ks][0] = qhp[r0 + off];
      qfh[ks][1] = qhp[r8 + off];
      qfh[ks][2] = qhp[r0 + off + 4];
      qfh[ks][3] = qhp[r8 + off + 4];
      qfl[ks][0] = qlp[r0 + off];
      qfl[ks][1] = qlp[r8 + off];
      qfl[ks][2] = qlp[r0 + off + 4];
      qfl[ks][3] = qlp[r8 + off + 4];
    }
  }

  float o[8][4];
#pragma unroll
  for (int j = 0; j < 8; j++)
#pragma unroll
    for (int r = 0; r < 4; r++) o[j][r] = 0.f;
  float m0 = -1e30f, m1 = -1e30f, l0 = 0.f, l1 = 0.f;

  issue_tile(kt0 * 64, smb_u);    // prologue: first tile -> buffer 0

  for (int kt = kt0; kt < kt1; kt++) {
    const int it = kt - kt0;
    const uint32_t kvb = smb_u + (uint32_t)(it & 1) * KVBUF_B;

    CP_WAIT0();
    __syncthreads();   // tile kt visible; prev compute done on other buffer
    if (kt + 1 < kt1)
      issue_tile((kt + 1) * 64, smb_u + (uint32_t)((it & 1) ^ 1) * KVBUF_B);

    // ---- S = Q K^T : warp rows x all 64 key cols (8 n8-tiles) ----
    float s[8][4];
#pragma unroll
    for (int j = 0; j < 8; j++)
#pragma unroll
      for (int r = 0; r < 4; r++) s[j][r] = 0.f;

    const uint32_t kB = kvb + bL;
#pragma unroll
    for (int ks = 0; ks < 4; ks++) {
#pragma unroll
      for (int ntp = 0; ntp < 4; ntp++) {
        unsigned kh[4], kl[4];
        ldsm4(kh, kB + ntp * JP_OFF + ks * 32);
        ldsm4(kl, kB + TILE_B + ntp * JP_OFF + ks * 32);
#pragma unroll
        for (int sub = 0; sub < 2; sub++) {
          const int j = ntp * 2 + sub;
          mma_bf16(s[j], qfh[ks], kh[sub * 2], kh[sub * 2 + 1]);
          mma_bf16(s[j], qfh[ks], kl[sub * 2], kl[sub * 2 + 1]);
          mma_bf16(s[j], qfl[ks], kh[sub * 2], kh[sub * 2 + 1]);
        }
      }
    }

    // ---- scale + causal mask (diagonal tile only) ----
    const int kbase = kt * 64;
    const int qi0 = qbase + warp * 16 + g;
    const int qi1 = qi0 + 8;
#pragma unroll
    for (int j = 0; j < 8; j++) {
      s[j][0] *= 0.125f; s[j][1] *= 0.125f;
      s[j][2] *= 0.125f; s[j][3] *= 0.125f;
      if (kt == qt) {
        int col0 = kbase + j * 8 + 2 * c;
        if (col0     > qi0) s[j][0] = -1e30f;
        if (col0 + 1 > qi0) s[j][1] = -1e30f;
        if (col0     > qi1) s[j][2] = -1e30f;
        if (col0 + 1 > qi1) s[j][3] = -1e30f;
      }
    }

    // ---- softmax: thread-local + 2 shfls (row fully inside warp) ----
    float mx0 = -1e30f, mx1 = -1e30f;
#pragma unroll
    for (int j = 0; j < 8; j++) {
      mx0 = fmaxf(mx0, fmaxf(s[j][0], s[j][1]));
      mx1 = fmaxf(mx1, fmaxf(s[j][2], s[j][3]));
    }
    mx0 = fmaxf(mx0, __shfl_xor_sync(0xffffffffu, mx0, 1));
    mx0 = fmaxf(mx0, __shfl_xor_sync(0xffffffffu, mx0, 2));
    mx1 = fmaxf(mx1, __shfl_xor_sync(0xffffffffu, mx1, 1));
    mx1 = fmaxf(mx1, __shfl_xor_sync(0xffffffffu, mx1, 2));
    float M0 = fmaxf(m0, mx0);
    float M1 = fmaxf(m1, mx1);
    float a0 = __expf(m0 - M0);
    float a1 = __expf(m1 - M1);
    m0 = M0; m1 = M1;

    float ps0 = 0.f, ps1 = 0.f;
#pragma unroll
    for (int j = 0; j < 8; j++) {
      s[j][0] = __expf(s[j][0] - M0);
      s[j][1] = __expf(s[j][1] - M0);
      s[j][2] = __expf(s[j][2] - M1);
      s[j][3] = __expf(s[j][3] - M1);
      ps0 += s[j][0] + s[j][1];
      ps1 += s[j][2] + s[j][3];
    }
    ps0 += __shfl_xor_sync(0xffffffffu, ps0, 1);
    ps0 += __shfl_xor_sync(0xffffffffu, ps0, 2);
    ps1 += __shfl_xor_sync(0xffffffffu, ps1, 1);
    ps1 += __shfl_xor_sync(0xffffffffu, ps1, 2);
    l0 = l0 * a0 + ps0;
    l1 = l1 * a1 + ps1;

    // ---- convert S accumulators -> P A-fragments (registers only) ----
    // a0=(g, k 2c:2c+1)=s[2ks][0:1], a1=(g+8)=s[2ks][2:3],
    // a2=(g, k 8+2c)=s[2ks+1][0:1], a3=(g+8)=s[2ks+1][2:3]
    unsigned pfh[4][4], pfl[4][4];
#pragma unroll
    for (int ks = 0; ks < 4; ks++) {
#pragma unroll
      for (int r = 0; r < 4; r++) {
        const int j = 2 * ks + (r >> 1);
        const int e = (r & 1) * 2;
        float p0 = s[j][e], p1 = s[j][e + 1];
        __nv_bfloat162 h2 = __floats2bfloat162_rn(p0, p1);
        float2 hf = __bfloat1622float2(h2);
        __nv_bfloat162 l2 = __floats2bfloat162_rn(p0 - hf.x, p1 - hf.y);
        pfh[ks][r] = *(unsigned*)&h2;
        pfl[ks][r] = *(unsigned*)&l2;
      }
    }

    // ---- O = diag(alpha) O + P V ----
#pragma unroll
    for (int j = 0; j < 8; j++) {
      o[j][0] *= a0; o[j][1] *= a0;
      o[j][2] *= a1; o[j][3] *= a1;
    }
    const uint32_t vB = kvb + 2 * TILE_B + bL;
#pragma unroll
    for (int ks = 0; ks < 4; ks++) {
#pragma unroll
      for (int ntp = 0; ntp < 4; ntp++) {
        unsigned vh[4], vl[4];
        ldsm4(vh, vB + ntp * JP_OFF + ks * 32);
        ldsm4(vl, vB + TILE_B + ntp * JP_OFF + ks * 32);
#pragma unroll
        for (int sub = 0; sub < 2; sub++) {
          const int j = ntp * 2 + sub;
          mma_bf16(o[j], pfh[ks], vh[sub * 2], vh[sub * 2 + 1]);
          mma_bf16(o[j], pfh[ks], vl[sub * 2], vl[sub * 2 + 1]);
          mma_bf16(o[j], pfl[ks], vh[sub * 2], vh[sub * 2 + 1]);
        }
      }
    }
  }

  // ---- epilogue ----
  if (!is_split) {
    float i0 = 1.0f / l0, i1 = 1.0f / l1;
    int ob0 = (bT + qbase + warp * 16 + g) * H_;
    int ob1 = ob0 + 8 * H_;
#pragma unroll
    for (int j = 0; j < 8; j++) {
      *(float2*)&out[ob0 + j * 8 + 2 * c] = make_float2(o[j][0] * i0, o[j][1] * i0);
      *(float2*)&out[ob1 + j * 8 + 2 * c] = make_float2(o[j][2] * i1, o[j][3] * i1);
    }
  } else {
    const int part = (b * 16 + (qt - 16)) * 2 + split;
    float* U = g_pU + (size_t)part * 4096;
    int ob0 = (warp * 16 + g) * 64;
    int ob1 = ob0 + 8 * 64;
#pragma unroll
    for (int j = 0; j < 8; j++) {
      *(float2*)&U[ob0 + j * 8 + 2 * c] = make_float2(o[j][0], o[j][1]);
      *(float2*)&U[ob1 + j * 8 + 2 * c] = make_float2(o[j][2], o[j][3]);
    }
    if (c == 0) {
      g_pm[part * 64 + warp * 16 + g]     = m0;
      g_pm[part * 64 + warp * 16 + 8 + g] = m1;
      g_pl[part * 64 + warp * 16 + g]     = l0;
      g_pl[part * 64 + warp * 16 + 8 + g] = l1;
    }
  }
}

// ---------------------------------------------------------------------------
// Kernel 3: combine split-K partials for qt = 16..31 (128 blocks x 256 thr).
// out = (e^{m1-m} U1 + e^{m2-m} U2) / (e^{m1-m} l1 + e^{m2-m} l2)
// ---------------------------------------------------------------------------
__global__ __launch_bounds__(256) void combine_kernel(float* __restrict__ out) {
  const int bx = blockIdx.x;          // 0..127
  const int b = bx >> 4, qi = bx & 15;
  const int qt = 16 + qi;
  const int p0 = (b * 16 + qi) * 2, p1 = p0 + 1;
  const int t = threadIdx.x;
  const int row = t >> 2, cb = (t & 3) * 16;

  float m1 = g_pm[p0 * 64 + row], m2 = g_pm[p1 * 64 + row];
  float l1 = g_pl[p0 * 64 + row], l2 = g_pl[p1 * 64 + row];
  float m = fmaxf(m1, m2);
  float a1 = __expf(m1 - m), a2 = __expf(m2 - m);
  float inv = 1.0f / (a1 * l1 + a2 * l2);
  float c1 = a1 * inv, c2 = a2 * inv;

  const float* U1 = g_pU + (size_t)p0 * 4096 + row * 64 + cb;
  const float* U2 = g_pU + (size_t)p1 * 4096 + row * 64 + cb;
  float* dst = out + ((size_t)(b * T_ + qt * 64 + row)) * H_ + cb;
#pragma unroll
  for (int s = 0; s < 4; s++) {
    float4 u1 = *(const float4*)(U1 + s * 4);
    float4 u2 = *(const float4*)(U2 + s * 4);
    float4 r;
    r.x = c1 * u1.x + c2 * u2.x;
    r.y = c1 * u1.y + c2 * u2.y;
    r.z = c1 * u1.z + c2 * u2.z;
    r.w = c1 * u1.w + c2 * u2.w;
    *(float4*)(dst + s * 4) = r;
  }
}

// ---------------------------------------------------------------------------
extern "C" void kernel_launch(void* const* d_in, const int* in_sizes, int n_in,
                              void* d_out, int out_size) {
  const float* x  = (const float*)d_in[0];
  const float* Wq = (const float*)d_in[1];
  const float* Wk = (const float*)d_in[2];
  const float* Wv = (const float*)d_in[3];
  float* out = (float*)d_out;

  cudaFuncSetAttribute(qkv_mma,
                       cudaFuncAttributeMaxDynamicSharedMemorySize, QKV_SMEM);
  cudaFuncSetAttribute(attn_kernel,
                       cudaFuncAttributeMaxDynamicSharedMemorySize,
                       ATT_SMEM_BYTES);

  wsplit_kernel<<<48, 256>>>(Wq, Wk, Wv);                   // ~5 us
  qkv_mma<<<M_TOTAL / 128, 256, QKV_SMEM>>>(x);             // ~56 us
  attn_kernel<<<B_ * 48, 128, ATT_SMEM_BYTES>>>(out);       // target ~44 us
  combine_kernel<<<128, 256>>>(out);                        // ~6 us
}

// round 14
// speedup vs baseline: 1.0674x; 1.0674x over previous
#include <cuda_runtime.h>
#include <cuda_bf16.h>
#include <cstdint>

#define B_ 8
#define T_ 2048
#define C_ 1024
#define H_ 64
#define M_TOTAL (B_ * T_)   // 16384 rows

// bf16 hi/lo split scratch (allocation-free rule: __device__ globals)
__device__ __align__(16) __nv_bfloat16 g_qh[M_TOTAL * H_];
__device__ __align__(16) __nv_bfloat16 g_ql[M_TOTAL * H_];
__device__ __align__(16) __nv_bfloat16 g_kh[M_TOTAL * H_];
__device__ __align__(16) __nv_bfloat16 g_kl[M_TOTAL * H_];
// V stored transposed per batch: [b][h][t]
__device__ __align__(16) __nv_bfloat16 g_vth[B_ * H_ * T_];
__device__ __align__(16) __nv_bfloat16 g_vtl[B_ * H_ * T_];
// Fused weight, transposed + split: row n = {q0..63, k0..63, v0..63}, k-major
__device__ __align__(16) __nv_bfloat16 g_wth[192 * 1024];
__device__ __align__(16) __nv_bfloat16 g_wtl[192 * 1024];
// Split-K partials: 8 batches x 16 heavy q-tiles x 2 splits
__device__ __align__(16) float g_pU[256 * 4096];
__device__ float g_pm[256 * 64];
__device__ float g_pl[256 * 64];

// ---------------------------------------------------------------------------
// Base-PTX helpers (sm_80+ only; compute_103 virtual arch blocks tcgen05)
// ---------------------------------------------------------------------------
__device__ __forceinline__ uint32_t smem_u32(const void* p) {
  uint32_t a;
  asm("{ .reg .u64 t; cvta.to.shared.u64 t, %1; cvt.u32.u64 %0, t; }"
      : "=r"(a) : "l"(p));
  return a;
}

__device__ __forceinline__ void mma_bf16(float d[4], const unsigned a[4],
                                         unsigned b0, unsigned b1) {
  asm volatile(
      "mma.sync.aligned.m16n8k16.row.col.f32.bf16.bf16.f32 "
      "{%0,%1,%2,%3}, {%4,%5,%6,%7}, {%8,%9}, {%0,%1,%2,%3};\n"
      : "+f"(d[0]), "+f"(d[1]), "+f"(d[2]), "+f"(d[3])
      : "r"(a[0]), "r"(a[1]), "r"(a[2]), "r"(a[3]), "r"(b0), "r"(b1));
}

__device__ __forceinline__ void ldsm4(unsigned r[4], uint32_t addr) {
  asm volatile(
      "ldmatrix.sync.aligned.m8n8.x4.shared.b16 {%0,%1,%2,%3}, [%4];\n"
      : "=r"(r[0]), "=r"(r[1]), "=r"(r[2]), "=r"(r[3]) : "r"(addr));
}

#define CP_ASYNC16(dst, src) \
  asm volatile("cp.async.cg.shared.global [%0], [%1], 16;\n" \
               :: "r"(dst), "l"(src))
#define CP_COMMIT() asm volatile("cp.async.commit_group;\n" ::: "memory")
#define CP_WAIT0()  asm volatile("cp.async.wait_group 0;\n" ::: "memory")
#define BARP(id) asm volatile("bar.sync %0, 64;" :: "r"(id) : "memory")

#define LDU(p) (*(const unsigned*)&(p))

// ---------------------------------------------------------------------------
// Kernel 0: coalesced weight transpose + hi/lo split (48 blocks). Unchanged.
// ---------------------------------------------------------------------------
__global__ __launch_bounds__(256) void wsplit_kernel(
    const float* __restrict__ Wq, const float* __restrict__ Wk,
    const float* __restrict__ Wv) {
  __shared__ float tile[64][65];
  const int t = threadIdx.x;
  const int w = blockIdx.x >> 4;          // 0..2
  const int k0 = (blockIdx.x & 15) * 64;  // k tile
  const float* W = (w == 0) ? Wq : (w == 1 ? Wk : Wv);

#pragma unroll
  for (int i = 0; i < 16; i++) {
    int idx = i * 256 + t;
    int r = idx >> 6, c = idx & 63;
    tile[r][c] = W[(size_t)(k0 + r) * H_ + c];
  }
  __syncthreads();

  const int h = t >> 2, seg = t & 3;
  union { __nv_bfloat16 b[16]; uint4 u[2]; } th, tl;
#pragma unroll
  for (int kk = 0; kk < 16; kk++) {
    float v = tile[seg * 16 + kk][h];
    __nv_bfloat16 hi = __float2bfloat16(v);
    th.b[kk] = hi;
    tl.b[kk] = __float2bfloat16(v - __bfloat162float(hi));
  }
  size_t base = (size_t)(w * 64 + h) * C_ + k0 + seg * 16;
  ((uint4*)(g_wth + base))[0] = th.u[0];
  ((uint4*)(g_wth + base))[1] = th.u[1];
  ((uint4*)(g_wtl + base))[0] = tl.u[0];
  ((uint4*)(g_wtl + base))[1] = tl.u[1];
}

// ---------------------------------------------------------------------------
// Kernel 1: QKV GEMM, BM=64 for 2 blocks/SM (16 warps/SM latency hiding).
// out[16384 x 192] = x @ W^T, 3-term bf16 split. BK=32, 8 warps = 2(M) x 4(N),
// warp tile 32 x 48 (acc[2][6][4] = 48 regs). ldsm + cp.async double buffer.
// smem/stage: Ah 5120 | Al 5120 | Bh 15360 | Bl 15360 = 40960; x2 = 81920.
// ---------------------------------------------------------------------------
#define A_STRIDE_B 80            // bytes per A/B smem row (40 bf16)
#define OFF_AH 0
#define OFF_AL 5120              // 64*80
#define OFF_BH 10240
#define OFF_BL 25600             // +192*80
#define ST_BYTES 40960
#define QKV_SMEM (2 * ST_BYTES)  // 81920
#define VTS 66                   // V transpose tile stride (bf16 elems)

__global__ __launch_bounds__(256, 2) void qkv_mma(const float* __restrict__ x) {
  extern __shared__ char sm[];
  const uint32_t sb = smem_u32(sm);
  const int t = threadIdx.x;
  const int lane = t & 31, warp = t >> 5;
  const int g = lane >> 2, c = lane & 3;
  const int lm = lane >> 3, lr = lane & 7;
  const int wm = warp >> 2;       // 0..1  (32 rows each)
  const int wn = warp & 3;        // 0..3  (48 cols each)
  const int row0 = blockIdx.x * 64;

  float acc[2][6][4];
#pragma unroll
  for (int mt = 0; mt < 2; mt++)
#pragma unroll
    for (int nt = 0; nt < 6; nt++)
#pragma unroll
      for (int r = 0; r < 4; r++) acc[mt][nt][r] = 0.f;

  // A staging: 4 threads per row, 8 floats each
  const int arow = t >> 2, aseg = t & 3;
  const float* xptr = x + (size_t)(row0 + arow) * C_ + aseg * 8;

  uint32_t aoff[2][2], boff[3][2];
#pragma unroll
  for (int mt = 0; mt < 2; mt++)
#pragma unroll
    for (int ks = 0; ks < 2; ks++)
      aoff[mt][ks] = (uint32_t)((wm * 32 + mt * 16 + (lm & 1) * 8 + lr) * A_STRIDE_B +
                                (ks * 16 + (lm >> 1) * 8) * 2);
#pragma unroll
  for (int pair = 0; pair < 3; pair++)
#pragma unroll
    for (int ks = 0; ks < 2; ks++)
      boff[pair][ks] = (uint32_t)((wn * 48 + pair * 16 + (lm >> 1) * 8 + lr) * A_STRIDE_B +
                                  (ks * 16 + (lm & 1) * 8) * 2);

  auto storeA = [&](uint32_t base, const float4 xr[2]) {
    union { __nv_bfloat16 b[8]; uint4 u; } hu, lu;
#pragma unroll
    for (int v4 = 0; v4 < 2; v4++) {
      const float* f = (const float*)&xr[v4];
#pragma unroll
      for (int e = 0; e < 4; e++) {
        __nv_bfloat16 hi = __float2bfloat16(f[e]);
        hu.b[v4 * 4 + e] = hi;
        lu.b[v4 * 4 + e] = __float2bfloat16(f[e] - __bfloat162float(hi));
      }
    }
    char* dst_h = sm + (base - sb) + OFF_AH + arow * A_STRIDE_B + aseg * 16;
    char* dst_l = sm + (base - sb) + OFF_AL + arow * A_STRIDE_B + aseg * 16;
    *(uint4*)dst_h = hu.u;
    *(uint4*)dst_l = lu.u;
  };

  auto issueB = [&](int kc, uint32_t base) {
#pragma unroll
    for (int i = 0; i < 3; i++) {
      int f = i * 256 + t;
      int row = f >> 2, seg = f & 3;
      uint32_t dh = base + OFF_BH + row * A_STRIDE_B + seg * 16;
      uint32_t dl = base + OFF_BL + row * A_STRIDE_B + seg * 16;
      const __nv_bfloat16* sh = g_wth + (size_t)row * C_ + kc * 32 + seg * 8;
      const __nv_bfloat16* sl = g_wtl + (size_t)row * C_ + kc * 32 + seg * 8;
      CP_ASYNC16(dh, sh);
      CP_ASYNC16(dl, sl);
    }
  };

  float4 xr[2];
#pragma unroll
  for (int i = 0; i < 2; i++) xr[i] = *(const float4*)(xptr + i * 4);
  storeA(sb, xr);
  issueB(0, sb);
  CP_COMMIT();
#pragma unroll
  for (int i = 0; i < 2; i++) xr[i] = *(const float4*)(xptr + 32 + i * 4);

  for (int kc = 0; kc < 32; kc++) {
    const uint32_t sbase = sb + (kc & 1) * ST_BYTES;
    const uint32_t nbase = sb + ((kc & 1) ^ 1) * ST_BYTES;

    CP_WAIT0();
    __syncthreads();

    if (kc + 1 < 32) {
      issueB(kc + 1, nbase);
      CP_COMMIT();
    }

#pragma unroll
    for (int ks = 0; ks < 2; ks++) {
      unsigned ah[2][4], al[2][4];
#pragma unroll
      for (int mt = 0; mt < 2; mt++) {
        ldsm4(ah[mt], sbase + OFF_AH + aoff[mt][ks]);
        ldsm4(al[mt], sbase + OFF_AL + aoff[mt][ks]);
      }
#pragma unroll
      for (int pair = 0; pair < 3; pair++) {
        unsigned bh[4], bl[4];
        ldsm4(bh, sbase + OFF_BH + boff[pair][ks]);
        ldsm4(bl, sbase + OFF_BL + boff[pair][ks]);
#pragma unroll
        for (int sub = 0; sub < 2; sub++) {
          const int nt = pair * 2 + sub;
          unsigned b0h = bh[sub * 2], b1h = bh[sub * 2 + 1];
          unsigned b0l = bl[sub * 2], b1l = bl[sub * 2 + 1];
#pragma unroll
          for (int mt = 0; mt < 2; mt++) {
            mma_bf16(acc[mt][nt], ah[mt], b0h, b1h);
            mma_bf16(acc[mt][nt], ah[mt], b0l, b1l);
            mma_bf16(acc[mt][nt], al[mt], b0h, b1h);
          }
        }
      }
    }

    if (kc + 1 < 32) {
      storeA(nbase, xr);
      if (kc + 2 < 32) {
#pragma unroll
        for (int i = 0; i < 2; i++)
          xr[i] = *(const float4*)(xptr + (kc + 2) * 32 + i * 4);
      }
    }
  }

  // ---- writeback q/k: coalesced bf16x2 pairs (R4-verified layout) ----
#pragma unroll
  for (int mt = 0; mt < 2; mt++) {
#pragma unroll
    for (int nt = 0; nt < 6; nt++) {
      int n0 = wn * 48 + nt * 8;
      int arr = n0 >> 6;
      if (arr < 2) {
        __nv_bfloat16* dh = arr ? g_kh : g_qh;
        __nv_bfloat16* dl = arr ? g_kl : g_ql;
        int hcol = (n0 & 63) + 2 * c;
        int r0 = row0 + wm * 32 + mt * 16 + g;
#pragma unroll
        for (int half = 0; half < 2; half++) {
          float d0 = acc[mt][nt][half * 2], d1 = acc[mt][nt][half * 2 + 1];
          int row = r0 + half * 8;
          __nv_bfloat162 hh = __floats2bfloat162_rn(d0, d1);
          float2 hf = __bfloat1622float2(hh);
          __nv_bfloat162 ll = __floats2bfloat162_rn(d0 - hf.x, d1 - hf.y);
          *(unsigned*)&dh[(size_t)row * H_ + hcol] = *(unsigned*)&hh;
          *(unsigned*)&dl[(size_t)row * H_ + hcol] = *(unsigned*)&ll;
        }
      }
    }
  }

  // ---- writeback V via smem transpose (R4-verified) ----
  __syncthreads();
  __nv_bfloat16* Vsh = (__nv_bfloat16*)sm;
  __nv_bfloat16* Vsl = Vsh + 64 * VTS;
#pragma unroll
  for (int mt = 0; mt < 2; mt++) {
#pragma unroll
    for (int nt = 0; nt < 6; nt++) {
      int n0 = wn * 48 + nt * 8;
      if ((n0 >> 6) == 2) {
        int h0 = (n0 - 128) + 2 * c;
        int rl0 = wm * 32 + mt * 16 + g;
#pragma unroll
        for (int half = 0; half < 2; half++) {
          float d0 = acc[mt][nt][half * 2], d1 = acc[mt][nt][half * 2 + 1];
          int rl = rl0 + half * 8;
          __nv_bfloat162 hh = __floats2bfloat162_rn(d0, d1);
          float2 hf = __bfloat1622float2(hh);
          __nv_bfloat162 ll = __floats2bfloat162_rn(d0 - hf.x, d1 - hf.y);
          *(unsigned*)&Vsh[rl * VTS + h0] = *(unsigned*)&hh;
          *(unsigned*)&Vsl[rl * VTS + h0] = *(unsigned*)&ll;
        }
      }
    }
  }
  __syncthreads();
  {
    const int bb = row0 >> 11;
    const int tt0 = row0 & 2047;
    const int h = t >> 2, seg = t & 3;    // 64 h-rows x 4 segments of 16
    union { __nv_bfloat16 b[16]; uint4 u[2]; } th, tl;
#pragma unroll
    for (int i = 0; i < 16; i++) {
      th.b[i] = Vsh[(seg * 16 + i) * VTS + h];
      tl.b[i] = Vsl[(seg * 16 + i) * VTS + h];
    }
    __nv_bfloat16* dsth = g_vth + (size_t)(bb * H_ + h) * T_ + tt0 + seg * 16;
    __nv_bfloat16* dstl = g_vtl + (size_t)(bb * H_ + h) * T_ + tt0 + seg * 16;
    ((uint4*)dsth)[0] = th.u[0];
    ((uint4*)dsth)[1] = th.u[1];
    ((uint4*)dstl)[0] = tl.u[0];
    ((uint4*)dstl)[1] = tl.u[1];
  }
}

// ---------------------------------------------------------------------------
// Kernel 2: causal flash attention with 2-way split-K (exact R10, 131.8us).
// Grid = 8 batches x 48 units. Per batch, step i in [0,16):
//   unit 3i, 3i+1 : splits 0/1 of qt = 31-i  (each <= 16 key tiles)
//   unit 3i+2     : single block for qt = 15-i
// ---------------------------------------------------------------------------
#define SKS 72
#define TILE_ELEMS (64 * SKS)                // 4608 bf16
#define TILE_B (TILE_ELEMS * 2)              // 9216 bytes
#define KVBUF_B (4 * TILE_B)                 // 36864 bytes per buffer
#define JP_OFF (16 * SKS * 2)                // 2304: +16 n-rows
#define P_OFF_B (2 * KVBUF_B)                // 73728: Ph; Pl at +TILE_B
#define RED_OFF_E (P_OFF_B / 2 + 2 * TILE_ELEMS)   // 46080 elems
#define ATT_SMEM_BYTES (P_OFF_B + 2 * TILE_B + 256 * 4)   // 93184

__global__ __launch_bounds__(256, 2) void attn_kernel(float* __restrict__ out) {
  extern __shared__ __nv_bfloat16 smb[];
  const uint32_t smb_u = smem_u32(smb);
  __nv_bfloat16* Ph = smb + P_OFF_B / 2;
  __nv_bfloat16* Pl = Ph + TILE_ELEMS;
  float* redmax = (float*)(smb + RED_OFF_E);
  float* redsum = redmax + 128;

  const int t = threadIdx.x;
  const int warp = t >> 5, lane = t & 31;
  const int g = lane >> 2, c = lane & 3;
  const int lm = lane >> 3, lr = lane & 7;
  const int wm = warp >> 1, wn = warp & 1;
  const int barid = 1 + wm;                 // named barrier per warp pair
  const int bx = blockIdx.x;
  const int b  = bx & 7;
  const int u  = bx >> 3;                   // 0..47
  const int stepi = u / 3;
  const int r3 = u - stepi * 3;

  int qt, kt0, kt1, split;
  bool is_split;
  if (r3 < 2) {
    qt = 31 - stepi;
    split = r3;
    int nk = qt + 1, half = nk >> 1;
    kt0 = split ? half : 0;
    kt1 = split ? nk : half;
    is_split = true;
  } else {
    qt = 15 - stepi;
    split = 0;
    kt0 = 0;
    kt1 = qt + 1;
    is_split = false;
  }

  const int bT = b * T_;
  const int qbase = qt * 64;

  const uint32_t bLane =
      ((wn * 32 + (lm >> 1) * 8 + lr) * SKS + (lm & 1) * 8) * 2;
  const uint32_t pA = smb_u + P_OFF_B +
      ((wm * 16 + (lm & 1) * 8 + lr) * SKS + (lm >> 1) * 8) * 2;

  auto issue_tile = [&](int kbase, uint32_t bufb) {
#pragma unroll
    for (int i = 0; i < 2; i++) {
      int id = i * 256 + t;
      int r = id >> 3, s = id & 7;
      uint32_t rowoff = (uint32_t)(r * (SKS * 2) + s * 16);
      CP_ASYNC16(bufb + rowoff,
                 g_kh + (size_t)(bT + kbase + r) * H_ + s * 8);
      CP_ASYNC16(bufb + TILE_B + rowoff,
                 g_kl + (size_t)(bT + kbase + r) * H_ + s * 8);
      CP_ASYNC16(bufb + 2 * TILE_B + rowoff,
                 g_vth + (size_t)(b * 64 + r) * T_ + kbase + s * 8);
      CP_ASYNC16(bufb + 3 * TILE_B + rowoff,
                 g_vtl + (size_t)(b * 64 + r) * T_ + kbase + s * 8);
    }
    CP_COMMIT();
  };

  unsigned qfh[4][4], qfl[4][4];
  {
    const unsigned* qhp = (const unsigned*)g_qh;
    const unsigned* qlp = (const unsigned*)g_ql;
    int r0 = (bT + qbase + wm * 16 + g) * 32;
    int r8 = r0 + 8 * 32;
#pragma unroll
    for (int ks = 0; ks < 4; ks++) {
      int off = ks * 8 + c;
      qfh[ks][0] = qhp[r0 + off];
      qfh[ks][1] = qhp[r8 + off];
      qfh[ks][2] = qhp[r0 + off + 4];
      qfh[ks][3] = qhp[r8 + off + 4];
      qfl[ks][0] = qlp[r0 + off];
      qfl[ks][1] = qlp[r8 + off];
      qfl[ks][2] = qlp[r0 + off + 4];
      qfl[ks][3] = qlp[r8 + off + 4];
    }
  }

  float o[4][4];
#pragma unroll
  for (int j = 0; j < 4; j++)
#pragma unroll
    for (int r = 0; r < 4; r++) o[j][r] = 0.f;
  float m0 = -1e30f, m1 = -1e30f, l0 = 0.f, l1 = 0.f;

  issue_tile(kt0 * 64, smb_u);

  for (int kt = kt0; kt < kt1; kt++) {
    const int it = kt - kt0;
    const uint32_t kvb = smb_u + (uint32_t)(it & 1) * KVBUF_B;

    CP_WAIT0();
    __syncthreads();
    if (kt + 1 < kt1)
      issue_tile((kt + 1) * 64, smb_u + (uint32_t)((it & 1) ^ 1) * KVBUF_B);

    float s[4][4];
#pragma unroll
    for (int j = 0; j < 4; j++)
#pragma unroll
      for (int r = 0; r < 4; r++) s[j][r] = 0.f;

    const uint32_t kB = kvb + bLane;
#pragma unroll
    for (int ks = 0; ks < 4; ks++) {
      unsigned kh0[4], kh1[4], kl0[4], kl1[4];
      ldsm4(kh0, kB + ks * 32);
      ldsm4(kh1, kB + JP_OFF + ks * 32);
      ldsm4(kl0, kB + TILE_B + ks * 32);
      ldsm4(kl1, kB + TILE_B + JP_OFF + ks * 32);
#pragma unroll
      for (int sub = 0; sub < 2; sub++) {
        mma_bf16(s[sub], qfh[ks], kh0[sub * 2], kh0[sub * 2 + 1]);
        mma_bf16(s[sub], qfh[ks], kl0[sub * 2], kl0[sub * 2 + 1]);
        mma_bf16(s[sub], qfl[ks], kh0[sub * 2], kh0[sub * 2 + 1]);
        mma_bf16(s[2 + sub], qfh[ks], kh1[sub * 2], kh1[sub * 2 + 1]);
        mma_bf16(s[2 + sub], qfh[ks], kl1[sub * 2], kl1[sub * 2 + 1]);
        mma_bf16(s[2 + sub], qfl[ks], kh1[sub * 2], kh1[sub * 2 + 1]);
      }
    }

    const int kbase = kt * 64;
    const int qi0 = qbase + wm * 16 + g;
    const int qi1 = qi0 + 8;
#pragma unroll
    for (int j = 0; j < 4; j++) {
      s[j][0] *= 0.125f; s[j][1] *= 0.125f;
      s[j][2] *= 0.125f; s[j][3] *= 0.125f;
      if (kt == qt) {
        int col0 = kbase + wn * 32 + j * 8 + 2 * c;
        if (col0     > qi0) s[j][0] = -1e30f;
        if (col0 + 1 > qi0) s[j][1] = -1e30f;
        if (col0     > qi1) s[j][2] = -1e30f;
        if (col0 + 1 > qi1) s[j][3] = -1e30f;
      }
    }

    float mx0 = -1e30f, mx1 = -1e30f;
#pragma unroll
    for (int j = 0; j < 4; j++) {
      mx0 = fmaxf(mx0, fmaxf(s[j][0], s[j][1]));
      mx1 = fmaxf(mx1, fmaxf(s[j][2], s[j][3]));
    }
    mx0 = fmaxf(mx0, __shfl_xor_sync(0xffffffffu, mx0, 1));
    mx0 = fmaxf(mx0, __shfl_xor_sync(0xffffffffu, mx0, 2));
    mx1 = fmaxf(mx1, __shfl_xor_sync(0xffffffffu, mx1, 1));
    mx1 = fmaxf(mx1, __shfl_xor_sync(0xffffffffu, mx1, 2));
    if (c == 0) {
      redmax[wn * 64 + wm * 16 + g]     = mx0;
      redmax[wn * 64 + wm * 16 + 8 + g] = mx1;
    }
    BARP(barid);
    float M0 = fmaxf(m0, fmaxf(mx0, redmax[(1 - wn) * 64 + wm * 16 + g]));
    float M1 = fmaxf(m1, fmaxf(mx1, redmax[(1 - wn) * 64 + wm * 16 + 8 + g]));
    float a0 = __expf(m0 - M0);
    float a1 = __expf(m1 - M1);
    m0 = M0; m1 = M1;

    float ps0 = 0.f, ps1 = 0.f;
#pragma unroll
    for (int j = 0; j < 4; j++) {
      float p00 = __expf(s[j][0] - M0);
      float p01 = __expf(s[j][1] - M0);
      float p10 = __expf(s[j][2] - M1);
      float p11 = __expf(s[j][3] - M1);
      ps0 += p00 + p01;
      ps1 += p10 + p11;
      int pr0 = (wm * 16 + g) * SKS + wn * 32 + j * 8 + 2 * c;
      int pr1 = pr0 + 8 * SKS;
      __nv_bfloat162 h2 = __floats2bfloat162_rn(p00, p01);
      float2 hf = __bfloat1622float2(h2);
      __nv_bfloat162 l2 = __floats2bfloat162_rn(p00 - hf.x, p01 - hf.y);
      *(unsigned*)&Ph[pr0] = *(unsigned*)&h2;
      *(unsigned*)&Pl[pr0] = *(unsigned*)&l2;
      __nv_bfloat162 h3 = __floats2bfloat162_rn(p10, p11);
      float2 hg = __bfloat1622float2(h3);
      __nv_bfloat162 l3 = __floats2bfloat162_rn(p10 - hg.x, p11 - hg.y);
      *(unsigned*)&Ph[pr1] = *(unsigned*)&h3;
      *(unsigned*)&Pl[pr1] = *(unsigned*)&l3;
    }
    ps0 += __shfl_xor_sync(0xffffffffu, ps0, 1);
    ps0 += __shfl_xor_sync(0xffffffffu, ps0, 2);
    ps1 += __shfl_xor_sync(0xffffffffu, ps1, 1);
    ps1 += __shfl_xor_sync(0xffffffffu, ps1, 2);
    if (c == 0) {
      redsum[wn * 64 + wm * 16 + g]     = ps0;
      redsum[wn * 64 + wm * 16 + 8 + g] = ps1;
    }
    BARP(barid);
    l0 = l0 * a0 + ps0 + redsum[(1 - wn) * 64 + wm * 16 + g];
    l1 = l1 * a1 + ps1 + redsum[(1 - wn) * 64 + wm * 16 + 8 + g];

#pragma unroll
    for (int j = 0; j < 4; j++) {
      o[j][0] *= a0; o[j][1] *= a0;
      o[j][2] *= a1; o[j][3] *= a1;
    }
    const uint32_t vB = kvb + 2 * TILE_B + bLane;
#pragma unroll
    for (int ks = 0; ks < 4; ks++) {
      unsigned ph[4], pl[4], vh0[4], vh1[4], vl0[4], vl1[4];
      ldsm4(ph, pA + ks * 32);
      ldsm4(pl, pA + TILE_B + ks * 32);
      ldsm4(vh0, vB + ks * 32);
      ldsm4(vh1, vB + JP_OFF + ks * 32);
      ldsm4(vl0, vB + TILE_B + ks * 32);
      ldsm4(vl1, vB + TILE_B + JP_OFF + ks * 32);
#pragma unroll
      for (int sub = 0; sub < 2; sub++) {
        mma_bf16(o[sub], ph, vh0[sub * 2], vh0[sub * 2 + 1]);
        mma_bf16(o[sub], ph, vl0[sub * 2], vl0[sub * 2 + 1]);
        mma_bf16(o[sub], pl, vh0[sub * 2], vh0[sub * 2 + 1]);
        mma_bf16(o[2 + sub], ph, vh1[sub * 2], vh1[sub * 2 + 1]);
        mma_bf16(o[2 + sub], ph, vl1[sub * 2], vl1[sub * 2 + 1]);
        mma_bf16(o[2 + sub], pl, vh1[sub * 2], vh1[sub * 2 + 1]);
      }
    }
  }

  if (!is_split) {
    float i0 = 1.0f / l0, i1 = 1.0f / l1;
    int ob0 = (bT + qbase + wm * 16 + g) * H_ + wn * 32;
    int ob1 = ob0 + 8 * H_;
#pragma unroll
    for (int j = 0; j < 4; j++) {
      float2 r0 = make_float2(o[j][0] * i0, o[j][1] * i0);
      float2 r1 = make_float2(o[j][2] * i1, o[j][3] * i1);
      *(float2*)&out[ob0 + j * 8 + 2 * c] = r0;
      *(float2*)&out[ob1 + j * 8 + 2 * c] = r1;
    }
  } else {
    const int part = (b * 16 + (qt - 16)) * 2 + split;
    float* U = g_pU + (size_t)part * 4096;
    int ob0 = (wm * 16 + g) * 64 + wn * 32;
    int ob1 = ob0 + 8 * 64;
#pragma unroll
    for (int j = 0; j < 4; j++) {
      *(float2*)&U[ob0 + j * 8 + 2 * c] = make_float2(o[j][0], o[j][1]);
      *(float2*)&U[ob1 + j * 8 + 2 * c] = make_float2(o[j][2], o[j][3]);
    }
    if (wn == 0 && c == 0) {
      g_pm[part * 64 + wm * 16 + g]     = m0;
      g_pm[part * 64 + wm * 16 + 8 + g] = m1;
      g_pl[part * 64 + wm * 16 + g]     = l0;
      g_pl[part * 64 + wm * 16 + 8 + g] = l1;
    }
  }
}

// ---------------------------------------------------------------------------
// Kernel 3: combine split-K partials (512 blocks x 128 threads for MLP).
// ---------------------------------------------------------------------------
__global__ __launch_bounds__(128) void combine_kernel(float* __restrict__ out) {
  const int bx = blockIdx.x;          // 0..511
  const int b = bx >> 6;
  const int qi = (bx >> 2) & 15;
  const int quarter = bx & 3;
  const int qt = 16 + qi;
  const int p0 = (b * 16 + qi) * 2, p1 = p0 + 1;
  const int t = threadIdx.x;
  const int row = quarter * 16 + (t >> 3), cb = (t & 7) * 8;

  float m1 = g_pm[p0 * 64 + row], m2 = g_pm[p1 * 64 + row];
  float l1 = g_pl[p0 * 64 + row], l2 = g_pl[p1 * 64 + row];
  float m = fmaxf(m1, m2);
  float a1 = __expf(m1 - m), a2 = __expf(m2 - m);
  float inv = 1.0f / (a1 * l1 + a2 * l2);
  float c1 = a1 * inv, c2 = a2 * inv;

  const float* U1 = g_pU + (size_t)p0 * 4096 + row * 64 + cb;
  const float* U2 = g_pU + (size_t)p1 * 4096 + row * 64 + cb;
  float* dst = out + ((size_t)(b * T_ + qt * 64 + row)) * H_ + cb;
#pragma unroll
  for (int s = 0; s < 2; s++) {
    float4 u1 = *(const float4*)(U1 + s * 4);
    float4 u2 = *(const float4*)(U2 + s * 4);
    float4 r;
    r.x = c1 * u1.x + c2 * u2.x;
    r.y = c1 * u1.y + c2 * u2.y;
    r.z = c1 * u1.z + c2 * u2.z;
    r.w = c1 * u1.w + c2 * u2.w;
    *(float4*)(dst + s * 4) = r;
  }
}

// ---------------------------------------------------------------------------
extern "C" void kernel_launch(void* const* d_in, const int* in_sizes, int n_in,
                              void* d_out, int out_size) {
  const float* x  = (const float*)d_in[0];
  const float* Wq = (const float*)d_in[1];
  const float* Wk = (const float*)d_in[2];
  const float* Wv = (const float*)d_in[3];
  float* out = (float*)d_out;

  cudaFuncSetAttribute(qkv_mma,
                       cudaFuncAttributeMaxDynamicSharedMemorySize, QKV_SMEM);
  cudaFuncSetAttribute(attn_kernel,
                       cudaFuncAttributeMaxDynamicSharedMemorySize,
                       ATT_SMEM_BYTES);

  wsplit_kernel<<<48, 256>>>(Wq, Wk, Wv);                   // ~5 us
  qkv_mma<<<M_TOTAL / 64, 256, QKV_SMEM>>>(x);              // target ~42 us
  attn_kernel<<<B_ * 48, 256, ATT_SMEM_BYTES>>>(out);       // ~64 us (R10)
  combine_kernel<<<512, 128>>>(out);                        // target ~4.5 us
}